// round 7
// baseline (speedup 1.0000x reference)
#include <cuda_runtime.h>
#include <cstdint>

#define BB 4
#define SS 1024
#define HH 32
#define DD 8
#define EE 256
constexpr int NROWS = BB * SS * HH;

// Scratch (allocation-free rule: __device__ globals)
__device__ float g_att[BB * SS * EE];       // [B,S,E] attention out, 4 MB

// ---------- packed f32x2 helpers (Blackwell dual FP32 datapath) ----------
__device__ __forceinline__ unsigned long long pack2(float lo, float hi) {
    unsigned long long r;
    asm("mov.b64 %0, {%1, %2};" : "=l"(r) : "f"(lo), "f"(hi));
    return r;
}
__device__ __forceinline__ void unpack2(unsigned long long v, float& lo, float& hi) {
    asm("mov.b64 {%0, %1}, %2;" : "=f"(lo), "=f"(hi) : "l"(v));
}
__device__ __forceinline__ unsigned long long ffma2(unsigned long long a,
                                                    unsigned long long b,
                                                    unsigned long long c) {
    unsigned long long d;
    asm("fma.rn.f32x2 %0, %1, %2, %3;" : "=l"(d) : "l"(a), "l"(b), "l"(c));
    return d;
}
__device__ __forceinline__ unsigned long long fadd2(unsigned long long a,
                                                    unsigned long long b) {
    unsigned long long d;
    asm("add.rn.f32x2 %0, %1, %2;" : "=l"(d) : "l"(a), "l"(b));
    return d;
}
__device__ __forceinline__ float ex2(float x) {
    float y;
    asm("ex2.approx.ftz.f32 %0, %1;" : "=f"(y) : "f"(x));
    return y;
}

// ---------------------------------------------------------------------------
// Fused kernel: quantum heads (closed form) + attention, R2-proven shape.
// Circuit closed form: <Z_w> = prod_{j=0..w} cos(x_j+th_j) (w>=1),
//                      <Z_0> = prod_{j=1..7} cos(x_j+th_j).
// Grid (128 heads, 8 slabs) x 128 threads  => 1024 blocks, ~7 blocks/SM.
// Phase 1: block builds the full head K(=Q=V) tile, pair-packed:
//          sF[p*16 + 2d + lane] = Z[2p+lane][d]   (32 KB).
// Phase 2: one query/thread; lanes carry two keys, q broadcast into both
// lanes (pre-scaled by log2(e)/sqrt(8)); 8-step ffma2 chain = two dots,
// ex2 per lane, AV accumulated as even/odd-key lane partials.
// |score| <= sqrt(8): single-pass softmax, no max subtraction.
// ---------------------------------------------------------------------------
__global__ void __launch_bounds__(128) attn_kernel(const float* __restrict__ x,
                                                   const float* __restrict__ theta) {
    __shared__ float sF[SS * 8];   // 32 KB pair-packed head tile

    int bh   = blockIdx.x;         // 0..127 (b*32 + h)
    int slab = blockIdx.y;         // 0..7
    int tid  = threadIdx.x;
    int b = bh >> 5, h = bh & 31;

    float th[8];
#pragma unroll
    for (int d = 0; d < 8; d++) th[d] = theta[d];

    // Phase 1: compute all 1024 head rows into pair-packed SMEM (8 rows/thread)
    for (int j = tid; j < SS; j += 128) {
        const float4* gx = reinterpret_cast<const float4*>(
            x + ((size_t)(b * SS + j) * EE + h * DD));
        float4 xa = gx[0];
        float4 xb = gx[1];

        float c[8];
        c[0] = cosf(xa.x + th[0]);
        c[1] = cosf(xa.y + th[1]);
        c[2] = cosf(xa.z + th[2]);
        c[3] = cosf(xa.w + th[3]);
        c[4] = cosf(xb.x + th[4]);
        c[5] = cosf(xb.y + th[5]);
        c[6] = cosf(xb.z + th[6]);
        c[7] = cosf(xb.w + th[7]);

        float z[8];
        float p = c[0];
#pragma unroll
        for (int w = 1; w < 8; w++) { p *= c[w]; z[w] = p; }
        float s = c[7];
#pragma unroll
        for (int w = 6; w >= 1; w--) s *= c[w];
        z[0] = s;

        int base = (j >> 1) * 16 + (j & 1);
#pragma unroll
        for (int d = 0; d < 8; d++) sF[base + 2 * d] = z[d];
    }
    __syncthreads();

    const float kS = 1.4426950408889634f / 2.8284271247461903f;  // log2(e)/sqrt(8)
    int sq = slab * 128 + tid;     // this thread's query row

    unsigned long long q2[8];
#pragma unroll
    for (int d = 0; d < 8; d++) {
        float qv = sF[(sq >> 1) * 16 + 2 * d + (sq & 1)] * kS;
        q2[d] = pack2(qv, qv);
    }

    unsigned long long o[8];
#pragma unroll
    for (int d = 0; d < 8; d++) o[d] = 0ULL;
    unsigned long long l2 = 0ULL;

    const ulonglong2* kp2 = reinterpret_cast<const ulonglong2*>(sF);

#pragma unroll 2
    for (int p = 0; p < SS / 2; p++) {
        ulonglong2 w01 = kp2[p * 4 + 0];
        ulonglong2 w23 = kp2[p * 4 + 1];
        ulonglong2 w45 = kp2[p * 4 + 2];
        ulonglong2 w67 = kp2[p * 4 + 3];

        unsigned long long acc = ffma2(q2[0], w01.x, 0ULL);
        acc = ffma2(q2[1], w01.y, acc);
        acc = ffma2(q2[2], w23.x, acc);
        acc = ffma2(q2[3], w23.y, acc);
        acc = ffma2(q2[4], w45.x, acc);
        acc = ffma2(q2[5], w45.y, acc);
        acc = ffma2(q2[6], w67.x, acc);
        acc = ffma2(q2[7], w67.y, acc);

        float s0, s1;
        unpack2(acc, s0, s1);
        unsigned long long pp = pack2(ex2(s0), ex2(s1));   // {p(key 2p), p(key 2p+1)}

        l2 = fadd2(l2, pp);
        o[0] = ffma2(pp, w01.x, o[0]);
        o[1] = ffma2(pp, w01.y, o[1]);
        o[2] = ffma2(pp, w23.x, o[2]);
        o[3] = ffma2(pp, w23.y, o[3]);
        o[4] = ffma2(pp, w45.x, o[4]);
        o[5] = ffma2(pp, w45.y, o[5]);
        o[6] = ffma2(pp, w67.x, o[6]);
        o[7] = ffma2(pp, w67.y, o[7]);
    }

    float ll, lh;
    unpack2(l2, ll, lh);
    float inv = 1.f / (ll + lh);

    float r[8];
#pragma unroll
    for (int d = 0; d < 8; d++) {
        float lo, hi;
        unpack2(o[d], lo, hi);
        r[d] = (lo + hi) * inv;
    }

    float* dst = g_att + ((size_t)(b * SS + sq)) * EE + h * DD;
    *reinterpret_cast<float4*>(dst)     = make_float4(r[0], r[1], r[2], r[3]);
    *reinterpret_cast<float4*>(dst + 4) = make_float4(r[4], r[5], r[6], r[7]);
}

// ---------------------------------------------------------------------------
// GEMM: out = g_att @ W^T.  M=4096, N=256, K=256, fp32.
// 64x64 tile, 128 threads, 4x8 micro-tile. Rows padded to 18 floats
// (72 B, 8B-aligned) so fragments are plain aligned 64-bit loads straight
// into f32x2 operands (compiler-tracked LDS.64 — NOT pure asm, so memory
// dependences across __syncthreads are honored).
// 12 LDS + 32 ffma2 per kk-pair per thread -> FMA-bound.
// ---------------------------------------------------------------------------
__global__ void __launch_bounds__(128) gemm_kernel(const float* __restrict__ W,
                                                   float* __restrict__ out) {
    __shared__ float As[64][18];   // [m][k] pad-18
    __shared__ float Bs[64][18];   // [n][k] pad-18

    int tid = threadIdx.x;
    int tx = tid & 7;              // n-group 0..7  -> cols tx*8..tx*8+7
    int ty = tid >> 3;             // m-group 0..15 -> rows ty*4..ty*4+3
    int m0 = blockIdx.y * 64, n0 = blockIdx.x * 64;

    unsigned long long acc2[4][8];
#pragma unroll
    for (int i = 0; i < 4; i++)
#pragma unroll
        for (int j = 0; j < 8; j++) acc2[i][j] = 0ULL;

    int lr = tid >> 1;             // 0..63
    int lc = (tid & 1) * 8;        // 0 or 8

    for (int k0 = 0; k0 < EE; k0 += 16) {
        // load 64x16 tiles (2 float4 per thread per tile)
        const float4* ga = reinterpret_cast<const float4*>(
            &g_att[(size_t)(m0 + lr) * EE + k0 + lc]);
        const float4* gb = reinterpret_cast<const float4*>(
            &W[(size_t)(n0 + lr) * EE + k0 + lc]);
        float4 a0 = ga[0], a1 = ga[1];
        float4 b0 = gb[0], b1 = gb[1];
        As[lr][lc + 0] = a0.x; As[lr][lc + 1] = a0.y;
        As[lr][lc + 2] = a0.z; As[lr][lc + 3] = a0.w;
        As[lr][lc + 4] = a1.x; As[lr][lc + 5] = a1.y;
        As[lr][lc + 6] = a1.z; As[lr][lc + 7] = a1.w;
        Bs[lr][lc + 0] = b0.x; Bs[lr][lc + 1] = b0.y;
        Bs[lr][lc + 2] = b0.z; Bs[lr][lc + 3] = b0.w;
        Bs[lr][lc + 4] = b1.x; Bs[lr][lc + 5] = b1.y;
        Bs[lr][lc + 6] = b1.z; Bs[lr][lc + 7] = b1.w;
        __syncthreads();

#pragma unroll
        for (int kk = 0; kk < 16; kk += 2) {
            unsigned long long a[4], bfr[8];
#pragma unroll
            for (int i = 0; i < 4; i++)
                a[i] = *reinterpret_cast<const unsigned long long*>(&As[ty * 4 + i][kk]);
#pragma unroll
            for (int j = 0; j < 8; j++)
                bfr[j] = *reinterpret_cast<const unsigned long long*>(&Bs[tx * 8 + j][kk]);
#pragma unroll
            for (int i = 0; i < 4; i++)
#pragma unroll
                for (int j = 0; j < 8; j++)
                    acc2[i][j] = ffma2(a[i], bfr[j], acc2[i][j]);
        }
        __syncthreads();
    }

#pragma unroll
    for (int i = 0; i < 4; i++) {
        float v[8];
#pragma unroll
        for (int j = 0; j < 8; j++) {
            float lo, hi;
            unpack2(acc2[i][j], lo, hi);
            v[j] = lo + hi;
        }
        float* dst = &out[(size_t)(m0 + ty * 4 + i) * EE + n0 + tx * 8];
        *reinterpret_cast<float4*>(dst)     = make_float4(v[0], v[1], v[2], v[3]);
        *reinterpret_cast<float4*>(dst + 4) = make_float4(v[4], v[5], v[6], v[7]);
    }
}

// ---------------------------------------------------------------------------
extern "C" void kernel_launch(void* const* d_in, const int* in_sizes, int n_in,
                              void* d_out, int out_size) {
    const float* x = nullptr;
    const float* theta = nullptr;
    const float* w = nullptr;
    for (int i = 0; i < n_in; i++) {
        if (in_sizes[i] == NROWS * DD)      x = (const float*)d_in[i];
        else if (in_sizes[i] == DD)         theta = (const float*)d_in[i];
        else if (in_sizes[i] == EE * EE)    w = (const float*)d_in[i];
    }

    attn_kernel<<<dim3(BB * HH, 8), 128>>>(x, theta);
    gemm_kernel<<<dim3(EE / 64, BB * SS / 64), 128>>>(w, (float*)d_out);
}

// round 8
// speedup vs baseline: 1.0767x; 1.0767x over previous
#include <cuda_runtime.h>
#include <cstdint>

#define BB 4
#define SS 1024
#define HH 32
#define DD 8
#define EE 256
constexpr int NROWS = BB * SS * HH;

// Scratch (allocation-free rule: __device__ globals)
__device__ float g_att[BB * SS * EE];       // [B,S,E] attention out, 4 MB

// ---------- packed f32x2 helpers (Blackwell dual FP32 datapath) ----------
__device__ __forceinline__ unsigned long long pack2(float lo, float hi) {
    unsigned long long r;
    asm("mov.b64 %0, {%1, %2};" : "=l"(r) : "f"(lo), "f"(hi));
    return r;
}
__device__ __forceinline__ void unpack2(unsigned long long v, float& lo, float& hi) {
    asm("mov.b64 {%0, %1}, %2;" : "=f"(lo), "=f"(hi) : "l"(v));
}
__device__ __forceinline__ unsigned long long ffma2(unsigned long long a,
                                                    unsigned long long b,
                                                    unsigned long long c) {
    unsigned long long d;
    asm("fma.rn.f32x2 %0, %1, %2, %3;" : "=l"(d) : "l"(a), "l"(b), "l"(c));
    return d;
}
__device__ __forceinline__ unsigned long long fadd2(unsigned long long a,
                                                    unsigned long long b) {
    unsigned long long d;
    asm("add.rn.f32x2 %0, %1, %2;" : "=l"(d) : "l"(a), "l"(b));
    return d;
}
__device__ __forceinline__ float ex2(float x) {
    float y;
    asm("ex2.approx.ftz.f32 %0, %1;" : "=f"(y) : "f"(x));
    return y;
}

// ---------------------------------------------------------------------------
// Fused kernel: quantum heads (closed form) + attention (UNCHANGED from R7,
// measured correct). Circuit closed form:
//   <Z_w> = prod_{j=0..w} cos(x_j+th_j) (w>=1), <Z_0> = prod_{j=1..7}.
// Grid (128 heads, 8 slabs) x 128 threads. Phase 1 builds pair-packed head
// tile in SMEM; phase 2: one query/thread, key-pair lanes, single-pass
// softmax (|score| <= sqrt(8), no max needed).
// ---------------------------------------------------------------------------
__global__ void __launch_bounds__(128) attn_kernel(const float* __restrict__ x,
                                                   const float* __restrict__ theta) {
    __shared__ float sF[SS * 8];   // 32 KB pair-packed head tile

    int bh   = blockIdx.x;         // 0..127 (b*32 + h)
    int slab = blockIdx.y;         // 0..7
    int tid  = threadIdx.x;
    int b = bh >> 5, h = bh & 31;

    float th[8];
#pragma unroll
    for (int d = 0; d < 8; d++) th[d] = theta[d];

    for (int j = tid; j < SS; j += 128) {
        const float4* gx = reinterpret_cast<const float4*>(
            x + ((size_t)(b * SS + j) * EE + h * DD));
        float4 xa = gx[0];
        float4 xb = gx[1];

        float c[8];
        c[0] = cosf(xa.x + th[0]);
        c[1] = cosf(xa.y + th[1]);
        c[2] = cosf(xa.z + th[2]);
        c[3] = cosf(xa.w + th[3]);
        c[4] = cosf(xb.x + th[4]);
        c[5] = cosf(xb.y + th[5]);
        c[6] = cosf(xb.z + th[6]);
        c[7] = cosf(xb.w + th[7]);

        float z[8];
        float p = c[0];
#pragma unroll
        for (int w = 1; w < 8; w++) { p *= c[w]; z[w] = p; }
        float s = c[7];
#pragma unroll
        for (int w = 6; w >= 1; w--) s *= c[w];
        z[0] = s;

        int base = (j >> 1) * 16 + (j & 1);
#pragma unroll
        for (int d = 0; d < 8; d++) sF[base + 2 * d] = z[d];
    }
    __syncthreads();

    const float kS = 1.4426950408889634f / 2.8284271247461903f;  // log2(e)/sqrt(8)
    int sq = slab * 128 + tid;

    unsigned long long q2[8];
#pragma unroll
    for (int d = 0; d < 8; d++) {
        float qv = sF[(sq >> 1) * 16 + 2 * d + (sq & 1)] * kS;
        q2[d] = pack2(qv, qv);
    }

    unsigned long long o[8];
#pragma unroll
    for (int d = 0; d < 8; d++) o[d] = 0ULL;
    unsigned long long l2 = 0ULL;

    const ulonglong2* kp2 = reinterpret_cast<const ulonglong2*>(sF);

#pragma unroll 2
    for (int p = 0; p < SS / 2; p++) {
        ulonglong2 w01 = kp2[p * 4 + 0];
        ulonglong2 w23 = kp2[p * 4 + 1];
        ulonglong2 w45 = kp2[p * 4 + 2];
        ulonglong2 w67 = kp2[p * 4 + 3];

        unsigned long long acc = ffma2(q2[0], w01.x, 0ULL);
        acc = ffma2(q2[1], w01.y, acc);
        acc = ffma2(q2[2], w23.x, acc);
        acc = ffma2(q2[3], w23.y, acc);
        acc = ffma2(q2[4], w45.x, acc);
        acc = ffma2(q2[5], w45.y, acc);
        acc = ffma2(q2[6], w67.x, acc);
        acc = ffma2(q2[7], w67.y, acc);

        float s0, s1;
        unpack2(acc, s0, s1);
        unsigned long long pp = pack2(ex2(s0), ex2(s1));

        l2 = fadd2(l2, pp);
        o[0] = ffma2(pp, w01.x, o[0]);
        o[1] = ffma2(pp, w01.y, o[1]);
        o[2] = ffma2(pp, w23.x, o[2]);
        o[3] = ffma2(pp, w23.y, o[3]);
        o[4] = ffma2(pp, w45.x, o[4]);
        o[5] = ffma2(pp, w45.y, o[5]);
        o[6] = ffma2(pp, w67.x, o[6]);
        o[7] = ffma2(pp, w67.y, o[7]);
    }

    float ll, lh;
    unpack2(l2, ll, lh);
    float inv = 1.f / (ll + lh);

    float r[8];
#pragma unroll
    for (int d = 0; d < 8; d++) {
        float lo, hi;
        unpack2(o[d], lo, hi);
        r[d] = (lo + hi) * inv;
    }

    float* dst = g_att + ((size_t)(b * SS + sq)) * EE + h * DD;
    *reinterpret_cast<float4*>(dst)     = make_float4(r[0], r[1], r[2], r[3]);
    *reinterpret_cast<float4*>(dst + 4) = make_float4(r[4], r[5], r[6], r[7]);
}

// ---------------------------------------------------------------------------
// GEMM: out = g_att @ W^T.  M=4096, N=256, K=256, fp32.  "n-lane" layout:
//   As[k][m]  = {A[m][k],  A[m][k]}        (dup, 8 KB / 16-k slab)
//   Bs[k][np] = {W[2np][k], W[2np+1][k]}   (n-pair lanes, 4 KB)
// Inner loop: per k-step 6 conflict-free LDS.64 + 8 ffma2 (2m x 4 n-pairs),
// zero packing. GMEM float4s register-double-buffered across slabs so LDG
// latency overlaps compute. 64x64 tile, 256 threads, grid 4x64.
// ---------------------------------------------------------------------------
__global__ void __launch_bounds__(256) gemm_kernel(const float* __restrict__ W,
                                                   float* __restrict__ out) {
    __shared__ unsigned long long As[16][64];   // [k][m] dup        8 KB
    __shared__ unsigned long long Bs[16][32];   // [k][np] n-pairs   4 KB
    float* BsF = reinterpret_cast<float*>(Bs);  // BsF[k*64 + n_local]

    int tid = threadIdx.x;
    int tx = tid & 7;              // n-pair group: np = tx + 8j
    int ty = tid >> 3;             // m rows: ty*2, ty*2+1
    int n0 = blockIdx.x * 64, m0 = blockIdx.y * 64;

    int lr  = tid & 63;            // loader row (m or n local)
    int lkq = tid >> 6;            // loader k-quad 0..3

    unsigned long long acc[2][4];
#pragma unroll
    for (int i = 0; i < 2; i++)
#pragma unroll
        for (int j = 0; j < 4; j++) acc[i][j] = 0ULL;

    const float* gA = &g_att[(size_t)(m0 + lr) * EE + lkq * 4];
    const float* gB = &W[(size_t)(n0 + lr) * EE + lkq * 4];

    float4 av = *reinterpret_cast<const float4*>(gA);
    float4 bv = *reinterpret_cast<const float4*>(gB);

    for (int k0 = 0; k0 < EE; k0 += 16) {
        // scatter current slab into transposed SMEM
        int kb = lkq * 4;
        As[kb + 0][lr] = pack2(av.x, av.x);
        As[kb + 1][lr] = pack2(av.y, av.y);
        As[kb + 2][lr] = pack2(av.z, av.z);
        As[kb + 3][lr] = pack2(av.w, av.w);
        BsF[(kb + 0) * 64 + lr] = bv.x;
        BsF[(kb + 1) * 64 + lr] = bv.y;
        BsF[(kb + 2) * 64 + lr] = bv.z;
        BsF[(kb + 3) * 64 + lr] = bv.w;
        __syncthreads();

        // prefetch next slab while computing
        if (k0 + 16 < EE) {
            av = *reinterpret_cast<const float4*>(gA + k0 + 16);
            bv = *reinterpret_cast<const float4*>(gB + k0 + 16);
        }

#pragma unroll
        for (int kk = 0; kk < 16; kk++) {
            unsigned long long a0 = As[kk][ty * 2];
            unsigned long long a1 = As[kk][ty * 2 + 1];
            unsigned long long b0 = Bs[kk][tx];
            unsigned long long b1 = Bs[kk][tx + 8];
            unsigned long long b2 = Bs[kk][tx + 16];
            unsigned long long b3 = Bs[kk][tx + 24];
            acc[0][0] = ffma2(a0, b0, acc[0][0]);
            acc[0][1] = ffma2(a0, b1, acc[0][1]);
            acc[0][2] = ffma2(a0, b2, acc[0][2]);
            acc[0][3] = ffma2(a0, b3, acc[0][3]);
            acc[1][0] = ffma2(a1, b0, acc[1][0]);
            acc[1][1] = ffma2(a1, b1, acc[1][1]);
            acc[1][2] = ffma2(a1, b2, acc[1][2]);
            acc[1][3] = ffma2(a1, b3, acc[1][3]);
        }
        __syncthreads();
    }

#pragma unroll
    for (int i = 0; i < 2; i++) {
        float* row = &out[(size_t)(m0 + ty * 2 + i) * EE + n0];
#pragma unroll
        for (int j = 0; j < 4; j++) {
            float lo, hi;
            unpack2(acc[i][j], lo, hi);
            *reinterpret_cast<float2*>(row + 2 * tx + 16 * j) = make_float2(lo, hi);
        }
    }
}

// ---------------------------------------------------------------------------
extern "C" void kernel_launch(void* const* d_in, const int* in_sizes, int n_in,
                              void* d_out, int out_size) {
    const float* x = nullptr;
    const float* theta = nullptr;
    const float* w = nullptr;
    for (int i = 0; i < n_in; i++) {
        if (in_sizes[i] == NROWS * DD)      x = (const float*)d_in[i];
        else if (in_sizes[i] == DD)         theta = (const float*)d_in[i];
        else if (in_sizes[i] == EE * EE)    w = (const float*)d_in[i];
    }

    attn_kernel<<<dim3(BB * HH, 8), 128>>>(x, theta);
    gemm_kernel<<<dim3(EE / 64, BB * SS / 64), 256>>>(w, (float*)d_out);
}

// round 9
// speedup vs baseline: 1.1047x; 1.0260x over previous
#include <cuda_runtime.h>
#include <cstdint>

#define BB 4
#define SS 1024
#define HH 32
#define DD 8
#define EE 256
constexpr int NROWS = BB * SS * HH;

// Scratch (allocation-free rule: __device__ globals)
__device__ float g_att[BB * SS * EE];       // [B,S,E] attention out, 4 MB

// ---------- packed f32x2 helpers (Blackwell dual FP32 datapath) ----------
__device__ __forceinline__ unsigned long long pack2(float lo, float hi) {
    unsigned long long r;
    asm("mov.b64 %0, {%1, %2};" : "=l"(r) : "f"(lo), "f"(hi));
    return r;
}
__device__ __forceinline__ void unpack2(unsigned long long v, float& lo, float& hi) {
    asm("mov.b64 {%0, %1}, %2;" : "=f"(lo), "=f"(hi) : "l"(v));
}
__device__ __forceinline__ unsigned long long ffma2(unsigned long long a,
                                                    unsigned long long b,
                                                    unsigned long long c) {
    unsigned long long d;
    asm("fma.rn.f32x2 %0, %1, %2, %3;" : "=l"(d) : "l"(a), "l"(b), "l"(c));
    return d;
}
__device__ __forceinline__ unsigned long long fadd2(unsigned long long a,
                                                    unsigned long long b) {
    unsigned long long d;
    asm("add.rn.f32x2 %0, %1, %2;" : "=l"(d) : "l"(a), "l"(b));
    return d;
}
__device__ __forceinline__ float ex2(float x) {
    float y;
    asm("ex2.approx.ftz.f32 %0, %1;" : "=f"(y) : "f"(x));
    return y;
}

// ---------------------------------------------------------------------------
// Fused kernel: quantum heads (closed form) + attention (UNCHANGED, verified).
// Circuit closed form: <Z_w> = prod_{j=0..w} cos(x_j+th_j) (w>=1),
//                      <Z_0> = prod_{j=1..7} cos(x_j+th_j).
// Grid (128 heads, 8 slabs) x 128 threads; pair-packed SMEM head tile;
// one query/thread with key-pair lanes; single-pass softmax (|s|<=sqrt(8)).
// ---------------------------------------------------------------------------
__global__ void __launch_bounds__(128) attn_kernel(const float* __restrict__ x,
                                                   const float* __restrict__ theta) {
    __shared__ float sF[SS * 8];   // 32 KB pair-packed head tile

    int bh   = blockIdx.x;         // 0..127 (b*32 + h)
    int slab = blockIdx.y;         // 0..7
    int tid  = threadIdx.x;
    int b = bh >> 5, h = bh & 31;

    float th[8];
#pragma unroll
    for (int d = 0; d < 8; d++) th[d] = theta[d];

    for (int j = tid; j < SS; j += 128) {
        const float4* gx = reinterpret_cast<const float4*>(
            x + ((size_t)(b * SS + j) * EE + h * DD));
        float4 xa = gx[0];
        float4 xb = gx[1];

        float c[8];
        c[0] = cosf(xa.x + th[0]);
        c[1] = cosf(xa.y + th[1]);
        c[2] = cosf(xa.z + th[2]);
        c[3] = cosf(xa.w + th[3]);
        c[4] = cosf(xb.x + th[4]);
        c[5] = cosf(xb.y + th[5]);
        c[6] = cosf(xb.z + th[6]);
        c[7] = cosf(xb.w + th[7]);

        float z[8];
        float p = c[0];
#pragma unroll
        for (int w = 1; w < 8; w++) { p *= c[w]; z[w] = p; }
        float s = c[7];
#pragma unroll
        for (int w = 6; w >= 1; w--) s *= c[w];
        z[0] = s;

        int base = (j >> 1) * 16 + (j & 1);
#pragma unroll
        for (int d = 0; d < 8; d++) sF[base + 2 * d] = z[d];
    }
    __syncthreads();

    const float kS = 1.4426950408889634f / 2.8284271247461903f;  // log2(e)/sqrt(8)
    int sq = slab * 128 + tid;

    unsigned long long q2[8];
#pragma unroll
    for (int d = 0; d < 8; d++) {
        float qv = sF[(sq >> 1) * 16 + 2 * d + (sq & 1)] * kS;
        q2[d] = pack2(qv, qv);
    }

    unsigned long long o[8];
#pragma unroll
    for (int d = 0; d < 8; d++) o[d] = 0ULL;
    unsigned long long l2 = 0ULL;

    const ulonglong2* kp2 = reinterpret_cast<const ulonglong2*>(sF);

#pragma unroll 2
    for (int p = 0; p < SS / 2; p++) {
        ulonglong2 w01 = kp2[p * 4 + 0];
        ulonglong2 w23 = kp2[p * 4 + 1];
        ulonglong2 w45 = kp2[p * 4 + 2];
        ulonglong2 w67 = kp2[p * 4 + 3];

        unsigned long long acc = ffma2(q2[0], w01.x, 0ULL);
        acc = ffma2(q2[1], w01.y, acc);
        acc = ffma2(q2[2], w23.x, acc);
        acc = ffma2(q2[3], w23.y, acc);
        acc = ffma2(q2[4], w45.x, acc);
        acc = ffma2(q2[5], w45.y, acc);
        acc = ffma2(q2[6], w67.x, acc);
        acc = ffma2(q2[7], w67.y, acc);

        float s0, s1;
        unpack2(acc, s0, s1);
        unsigned long long pp = pack2(ex2(s0), ex2(s1));

        l2 = fadd2(l2, pp);
        o[0] = ffma2(pp, w01.x, o[0]);
        o[1] = ffma2(pp, w01.y, o[1]);
        o[2] = ffma2(pp, w23.x, o[2]);
        o[3] = ffma2(pp, w23.y, o[3]);
        o[4] = ffma2(pp, w45.x, o[4]);
        o[5] = ffma2(pp, w45.y, o[5]);
        o[6] = ffma2(pp, w67.x, o[6]);
        o[7] = ffma2(pp, w67.y, o[7]);
    }

    float ll, lh;
    unpack2(l2, ll, lh);
    float inv = 1.f / (ll + lh);

    float r[8];
#pragma unroll
    for (int d = 0; d < 8; d++) {
        float lo, hi;
        unpack2(o[d], lo, hi);
        r[d] = (lo + hi) * inv;
    }

    float* dst = g_att + ((size_t)(b * SS + sq)) * EE + h * DD;
    *reinterpret_cast<float4*>(dst)     = make_float4(r[0], r[1], r[2], r[3]);
    *reinterpret_cast<float4*>(dst + 4) = make_float4(r[4], r[5], r[6], r[7]);
}

// ---------------------------------------------------------------------------
// GEMM: out = g_att @ W^T.  M=4096, N=256, K=256, fp32.
// Tile 32m x 64n, 128 threads, grid (4, 128) = 512 blocks.
// B chunk [64 n][128 k] stored transposed BsF[k*64+n] (32 KB); only 2 chunks
// => 4 __syncthreads total. A is streamed GMEM->regs (warp-broadcast LDG,
// L1/L2 resident), so no A SMEM and no per-slab sync. Inner loop per k:
// 4 conflict-free LDS.64 (n-pairs) + 2 dup-movs + 8 ffma2 -> FMA-bound.
// ---------------------------------------------------------------------------
__global__ void __launch_bounds__(128) gemm_kernel(const float* __restrict__ W,
                                                   float* __restrict__ out) {
    __shared__ float BsF[128 * 64];    // 32 KB: BsF[k*64 + n_local]

    int tid = threadIdx.x;
    int tx = tid & 7;                  // n-pair groups: pairs tx+8j (j=0..3)
    int ty = tid >> 3;                 // m rows ty*2, ty*2+1
    int n0 = blockIdx.x * 64, m0 = blockIdx.y * 32;

    unsigned long long acc[2][4];
#pragma unroll
    for (int i = 0; i < 2; i++)
#pragma unroll
        for (int j = 0; j < 4; j++) acc[i][j] = 0ULL;

    const float* gA0 = &g_att[(size_t)(m0 + ty * 2) * EE];
    const float* gA1 = gA0 + EE;

    for (int kc = 0; kc < EE; kc += 128) {
        // ---- load B chunk transposed: BsF[k][n] = W[n0+n][kc+k] ----
        __syncthreads();               // protect previous chunk's consumers
#pragma unroll
        for (int it = 0; it < 16; it++) {
            int idx = tid + it * 128;  // 2048 float4-slots: (r, c4)
            int r  = idx & 63;         // n_local, lanes -> distinct banks
            int c4 = idx >> 6;         // k quad 0..31
            float4 v = *reinterpret_cast<const float4*>(
                &W[(size_t)(n0 + r) * EE + kc + c4 * 4]);
            BsF[(c4 * 4 + 0) * 64 + r] = v.x;
            BsF[(c4 * 4 + 1) * 64 + r] = v.y;
            BsF[(c4 * 4 + 2) * 64 + r] = v.z;
            BsF[(c4 * 4 + 3) * 64 + r] = v.w;
        }
        __syncthreads();

        // ---- compute over this k chunk, A streamed from GMEM ----
        const unsigned long long* Bk = reinterpret_cast<const unsigned long long*>(BsF);
#pragma unroll 4
        for (int k4 = 0; k4 < 32; k4++) {
            float4 a0v = *reinterpret_cast<const float4*>(gA0 + kc + k4 * 4);
            float4 a1v = *reinterpret_cast<const float4*>(gA1 + kc + k4 * 4);
            float a0s[4] = {a0v.x, a0v.y, a0v.z, a0v.w};
            float a1s[4] = {a1v.x, a1v.y, a1v.z, a1v.w};
#pragma unroll
            for (int kk = 0; kk < 4; kk++) {
                int k = k4 * 4 + kk;
                unsigned long long a0 = pack2(a0s[kk], a0s[kk]);
                unsigned long long a1 = pack2(a1s[kk], a1s[kk]);
                unsigned long long b0 = Bk[k * 32 + tx];
                unsigned long long b1 = Bk[k * 32 + tx + 8];
                unsigned long long b2 = Bk[k * 32 + tx + 16];
                unsigned long long b3 = Bk[k * 32 + tx + 24];
                acc[0][0] = ffma2(a0, b0, acc[0][0]);
                acc[0][1] = ffma2(a0, b1, acc[0][1]);
                acc[0][2] = ffma2(a0, b2, acc[0][2]);
                acc[0][3] = ffma2(a0, b3, acc[0][3]);
                acc[1][0] = ffma2(a1, b0, acc[1][0]);
                acc[1][1] = ffma2(a1, b1, acc[1][1]);
                acc[1][2] = ffma2(a1, b2, acc[1][2]);
                acc[1][3] = ffma2(a1, b3, acc[1][3]);
            }
        }
    }

#pragma unroll
    for (int i = 0; i < 2; i++) {
        float* row = &out[(size_t)(m0 + ty * 2 + i) * EE + n0];
#pragma unroll
        for (int j = 0; j < 4; j++) {
            float lo, hi;
            unpack2(acc[i][j], lo, hi);
            *reinterpret_cast<float2*>(row + 2 * tx + 16 * j) = make_float2(lo, hi);
        }
    }
}

// ---------------------------------------------------------------------------
extern "C" void kernel_launch(void* const* d_in, const int* in_sizes, int n_in,
                              void* d_out, int out_size) {
    const float* x = nullptr;
    const float* theta = nullptr;
    const float* w = nullptr;
    for (int i = 0; i < n_in; i++) {
        if (in_sizes[i] == NROWS * DD)      x = (const float*)d_in[i];
        else if (in_sizes[i] == DD)         theta = (const float*)d_in[i];
        else if (in_sizes[i] == EE * EE)    w = (const float*)d_in[i];
    }

    attn_kernel<<<dim3(BB * HH, 8), 128>>>(x, theta);
    gemm_kernel<<<dim3(EE / 64, BB * SS / 32), 128>>>(w, (float*)d_out);
}

// round 11
// speedup vs baseline: 1.1827x; 1.0707x over previous
#include <cuda_runtime.h>
#include <cstdint>

#define BB 4
#define SS 1024
#define HH 32
#define DD 8
#define EE 256
constexpr int NROWS = BB * SS * HH;            // 131072
constexpr int NQ = BB * HH * SS;               // 131072 (rows x heads)

// Scratch (allocation-free rule: __device__ globals)
__device__ float g_att[BB * SS * EE];          // [B,S,E] attention out, 4 MB
__device__ float g_po[2][NQ][8];               // split-K partial o, 8 MB
__device__ float g_pl[2][NQ];                  // split-K partial l, 1 MB

// ---------- packed f32x2 helpers (Blackwell dual FP32 datapath) ----------
__device__ __forceinline__ unsigned long long pack2(float lo, float hi) {
    unsigned long long r;
    asm("mov.b64 %0, {%1, %2};" : "=l"(r) : "f"(lo), "f"(hi));
    return r;
}
__device__ __forceinline__ void unpack2(unsigned long long v, float& lo, float& hi) {
    asm("mov.b64 {%0, %1}, %2;" : "=f"(lo), "=f"(hi) : "l"(v));
}
__device__ __forceinline__ unsigned long long ffma2(unsigned long long a,
                                                    unsigned long long b,
                                                    unsigned long long c) {
    unsigned long long d;
    asm("fma.rn.f32x2 %0, %1, %2, %3;" : "=l"(d) : "l"(a), "l"(b), "l"(c));
    return d;
}
__device__ __forceinline__ unsigned long long fadd2(unsigned long long a,
                                                    unsigned long long b) {
    unsigned long long d;
    asm("add.rn.f32x2 %0, %1, %2;" : "=l"(d) : "l"(a), "l"(b));
    return d;
}
__device__ __forceinline__ float ex2(float x) {
    float y;
    asm("ex2.approx.ftz.f32 %0, %1;" : "=f"(y) : "f"(x));
    return y;
}

// ---------------------------------------------------------------------------
// Attention, split-K over 2 key-halves. Circuit closed form:
//   <Z_w> = prod_{j=0..w} cos(x_j+th_j) (w>=1), <Z_0> = prod_{j=1..7}.
// Grid (128 heads, 8 q-slabs, 2 key-halves) x 128 threads.
// Phase 1: block builds its 512-key half tile, pair-packed:
//          sF[p*16 + 2d + lane] = Z[2p+lane][d]  (16 KB -> ~9 blocks/SM).
// Each thread computes its own q row closed-form from x (identical fp ops).
// Phase 2: one query/thread, key-pair lanes, 8-step ffma2 chain = two dots,
// ex2 per lane, AV in even/odd-key lane partials. |score|<=sqrt(8): no max.
// Writes UNNORMALIZED partials (sum p*K, sum p); combine kernel reduces.
// ---------------------------------------------------------------------------
__global__ void __launch_bounds__(128) attn_kernel(const float* __restrict__ x,
                                                   const float* __restrict__ theta) {
    __shared__ float sF[512 * 8];   // 16 KB pair-packed half tile

    int bh   = blockIdx.x;          // 0..127 (b*32 + h)
    int slab = blockIdx.y;          // 0..7
    int kh   = blockIdx.z;          // 0..1 key half
    int tid  = threadIdx.x;
    int b = bh >> 5, h = bh & 31;

    float th[8];
#pragma unroll
    for (int d = 0; d < 8; d++) th[d] = theta[d];

    // Phase 1: key half tile (512 rows, 4/thread)
    for (int j = tid; j < 512; j += 128) {
        int row = kh * 512 + j;
        const float4* gx = reinterpret_cast<const float4*>(
            x + ((size_t)(b * SS + row) * EE + h * DD));
        float4 xa = gx[0];
        float4 xb = gx[1];

        float c[8];
        c[0] = cosf(xa.x + th[0]);
        c[1] = cosf(xa.y + th[1]);
        c[2] = cosf(xa.z + th[2]);
        c[3] = cosf(xa.w + th[3]);
        c[4] = cosf(xb.x + th[4]);
        c[5] = cosf(xb.y + th[5]);
        c[6] = cosf(xb.z + th[6]);
        c[7] = cosf(xb.w + th[7]);

        float z[8];
        float p = c[0];
#pragma unroll
        for (int w = 1; w < 8; w++) { p *= c[w]; z[w] = p; }
        float s = c[7];
#pragma unroll
        for (int w = 6; w >= 1; w--) s *= c[w];
        z[0] = s;

        int base = (j >> 1) * 16 + (j & 1);
#pragma unroll
        for (int d = 0; d < 8; d++) sF[base + 2 * d] = z[d];
    }

    // This thread's query row, computed directly (same fp sequence as keys)
    const float kS = 1.4426950408889634f / 2.8284271247461903f;  // log2(e)/sqrt(8)
    int sq = slab * 128 + tid;
    unsigned long long q2[8];
    {
        const float4* gx = reinterpret_cast<const float4*>(
            x + ((size_t)(b * SS + sq) * EE + h * DD));
        float4 xa = gx[0];
        float4 xb = gx[1];

        float c[8];
        c[0] = cosf(xa.x + th[0]);
        c[1] = cosf(xa.y + th[1]);
        c[2] = cosf(xa.z + th[2]);
        c[3] = cosf(xa.w + th[3]);
        c[4] = cosf(xb.x + th[4]);
        c[5] = cosf(xb.y + th[5]);
        c[6] = cosf(xb.z + th[6]);
        c[7] = cosf(xb.w + th[7]);

        float z[8];
        float p = c[0];
#pragma unroll
        for (int w = 1; w < 8; w++) { p *= c[w]; z[w] = p; }
        float s = c[7];
#pragma unroll
        for (int w = 6; w >= 1; w--) s *= c[w];
        z[0] = s;
#pragma unroll
        for (int d = 0; d < 8; d++) {
            float qv = z[d] * kS;
            q2[d] = pack2(qv, qv);
        }
    }
    __syncthreads();

    unsigned long long o[8];
#pragma unroll
    for (int d = 0; d < 8; d++) o[d] = 0ULL;
    unsigned long long l2 = 0ULL;

    const ulonglong2* kp2 = reinterpret_cast<const ulonglong2*>(sF);

#pragma unroll 2
    for (int p = 0; p < 256; p++) {
        ulonglong2 w01 = kp2[p * 4 + 0];
        ulonglong2 w23 = kp2[p * 4 + 1];
        ulonglong2 w45 = kp2[p * 4 + 2];
        ulonglong2 w67 = kp2[p * 4 + 3];

        unsigned long long acc = ffma2(q2[0], w01.x, 0ULL);
        acc = ffma2(q2[1], w01.y, acc);
        acc = ffma2(q2[2], w23.x, acc);
        acc = ffma2(q2[3], w23.y, acc);
        acc = ffma2(q2[4], w45.x, acc);
        acc = ffma2(q2[5], w45.y, acc);
        acc = ffma2(q2[6], w67.x, acc);
        acc = ffma2(q2[7], w67.y, acc);

        float s0, s1;
        unpack2(acc, s0, s1);
        unsigned long long pp = pack2(ex2(s0), ex2(s1));

        l2 = fadd2(l2, pp);
        o[0] = ffma2(pp, w01.x, o[0]);
        o[1] = ffma2(pp, w01.y, o[1]);
        o[2] = ffma2(pp, w23.x, o[2]);
        o[3] = ffma2(pp, w23.y, o[3]);
        o[4] = ffma2(pp, w45.x, o[4]);
        o[5] = ffma2(pp, w45.y, o[5]);
        o[6] = ffma2(pp, w67.x, o[6]);
        o[7] = ffma2(pp, w67.y, o[7]);
    }

    float ll, lh;
    unpack2(l2, ll, lh);

    float r[8];
#pragma unroll
    for (int d = 0; d < 8; d++) {
        float lo, hi;
        unpack2(o[d], lo, hi);
        r[d] = lo + hi;
    }

    int rowid = bh * SS + sq;
    float* po = &g_po[kh][rowid][0];
    *reinterpret_cast<float4*>(po)     = make_float4(r[0], r[1], r[2], r[3]);
    *reinterpret_cast<float4*>(po + 4) = make_float4(r[4], r[5], r[6], r[7]);
    g_pl[kh][rowid] = ll + lh;
}

// ---------------------------------------------------------------------------
// Combine: sum the two key-half partials, normalize, scatter to [B,S,E].
// ---------------------------------------------------------------------------
__global__ void __launch_bounds__(256) combine_kernel() {
    int n = blockIdx.x * 256 + threadIdx.x;    // 0..131071

    const float4* p0 = reinterpret_cast<const float4*>(&g_po[0][n][0]);
    const float4* p1 = reinterpret_cast<const float4*>(&g_po[1][n][0]);
    float4 a0 = p0[0], a1 = p0[1];
    float4 b0 = p1[0], b1 = p1[1];
    float inv = 1.f / (g_pl[0][n] + g_pl[1][n]);

    int bh = n >> 10, sq = n & 1023;
    int b = bh >> 5, h = bh & 31;
    float* dst = g_att + ((size_t)(b * SS + sq)) * EE + h * DD;
    *reinterpret_cast<float4*>(dst) = make_float4(
        (a0.x + b0.x) * inv, (a0.y + b0.y) * inv,
        (a0.z + b0.z) * inv, (a0.w + b0.w) * inv);
    *reinterpret_cast<float4*>(dst + 4) = make_float4(
        (a1.x + b1.x) * inv, (a1.y + b1.y) * inv,
        (a1.z + b1.z) * inv, (a1.w + b1.w) * inv);
}

// ---------------------------------------------------------------------------
// GEMM: out = g_att @ W^T.  M=4096, N=256, K=256, fp32.
// Tile 64m x 64n, 128 threads, micro 4m x 8n (4x4 packed accs).
// FULL B tile [256 k][64 n] transposed in 64 KB dynamic SMEM, loaded once,
// ONE sync. Each B LDS.64 feeds 4 ffma2 -> LDS demand ~= FMA demand on
// separate pipes. A streamed GMEM->regs with one-k8-group-ahead prefetch
// (256 FMA-issue cycles > L2 latency).
// ---------------------------------------------------------------------------
__global__ void __launch_bounds__(128) gemm_kernel(const float* __restrict__ W,
                                                   float* __restrict__ out) {
    extern __shared__ float BsF[];     // 64 KB: BsF[k*64 + n_local]

    int tid = threadIdx.x;
    int tx = tid & 7;                  // n-pair groups: pairs tx+8j (j=0..3)
    int ty = tid >> 3;                 // m rows ty*4 .. ty*4+3
    int n0 = blockIdx.x * 64, m0 = blockIdx.y * 64;

    // ---- load whole B tile transposed (32 float4 per thread) ----
#pragma unroll
    for (int it = 0; it < 32; it++) {
        int idx = tid + it * 128;      // 4096 float4-slots
        int r  = idx & 63;             // n_local
        int c4 = idx >> 6;             // k-quad 0..63
        float4 v = *reinterpret_cast<const float4*>(
            &W[(size_t)(n0 + r) * EE + c4 * 4]);
        BsF[(c4 * 4 + 0) * 64 + r] = v.x;
        BsF[(c4 * 4 + 1) * 64 + r] = v.y;
        BsF[(c4 * 4 + 2) * 64 + r] = v.z;
        BsF[(c4 * 4 + 3) * 64 + r] = v.w;
    }
    __syncthreads();

    unsigned long long acc[4][4];
#pragma unroll
    for (int i = 0; i < 4; i++)
#pragma unroll
        for (int j = 0; j < 4; j++) acc[i][j] = 0ULL;

    const float* gA[4];
#pragma unroll
    for (int i = 0; i < 4; i++)
        gA[i] = &g_att[(size_t)(m0 + ty * 4 + i) * EE];

    const unsigned long long* Bk = reinterpret_cast<const unsigned long long*>(BsF);

    // prefetch first k8 group (4 rows x 2 quads)
    float4 cur[4][2];
#pragma unroll
    for (int i = 0; i < 4; i++) {
        cur[i][0] = *reinterpret_cast<const float4*>(gA[i] + 0);
        cur[i][1] = *reinterpret_cast<const float4*>(gA[i] + 4);
    }

    for (int k8 = 0; k8 < EE; k8 += 8) {
        float4 nxt[4][2];
        if (k8 + 8 < EE) {
#pragma unroll
            for (int i = 0; i < 4; i++) {
                nxt[i][0] = *reinterpret_cast<const float4*>(gA[i] + k8 + 8);
                nxt[i][1] = *reinterpret_cast<const float4*>(gA[i] + k8 + 12);
            }
        }

#pragma unroll
        for (int q = 0; q < 2; q++) {
#pragma unroll
            for (int kk = 0; kk < 4; kk++) {
                int k = k8 + q * 4 + kk;
                unsigned long long b0 = Bk[k * 32 + tx];
                unsigned long long b1 = Bk[k * 32 + tx + 8];
                unsigned long long b2 = Bk[k * 32 + tx + 16];
                unsigned long long b3 = Bk[k * 32 + tx + 24];
#pragma unroll
                for (int i = 0; i < 4; i++) {
                    float av = (kk == 0) ? cur[i][q].x :
                               (kk == 1) ? cur[i][q].y :
                               (kk == 2) ? cur[i][q].z : cur[i][q].w;
                    unsigned long long ad = pack2(av, av);
                    acc[i][0] = ffma2(ad, b0, acc[i][0]);
                    acc[i][1] = ffma2(ad, b1, acc[i][1]);
                    acc[i][2] = ffma2(ad, b2, acc[i][2]);
                    acc[i][3] = ffma2(ad, b3, acc[i][3]);
                }
            }
        }

        if (k8 + 8 < EE) {
#pragma unroll
            for (int i = 0; i < 4; i++) {
                cur[i][0] = nxt[i][0];
                cur[i][1] = nxt[i][1];
            }
        }
    }

#pragma unroll
    for (int i = 0; i < 4; i++) {
        float* row = &out[(size_t)(m0 + ty * 4 + i) * EE + n0];
#pragma unroll
        for (int j = 0; j < 4; j++) {
            float lo, hi;
            unpack2(acc[i][j], lo, hi);
            *reinterpret_cast<float2*>(row + 2 * tx + 16 * j) = make_float2(lo, hi);
        }
    }
}

// ---------------------------------------------------------------------------
constexpr int GEMM_SMEM = 64 * EE * 4;   // 65536 bytes

extern "C" void kernel_launch(void* const* d_in, const int* in_sizes, int n_in,
                              void* d_out, int out_size) {
    const float* x = nullptr;
    const float* theta = nullptr;
    const float* w = nullptr;
    for (int i = 0; i < n_in; i++) {
        if (in_sizes[i] == NROWS * DD)      x = (const float*)d_in[i];
        else if (in_sizes[i] == DD)         theta = (const float*)d_in[i];
        else if (in_sizes[i] == EE * EE)    w = (const float*)d_in[i];
    }

    // Host-side attribute set: graph-capture-safe, deterministic.
    cudaFuncSetAttribute(gemm_kernel,
                         cudaFuncAttributeMaxDynamicSharedMemorySize, GEMM_SMEM);

    attn_kernel<<<dim3(BB * HH, 8, 2), 128>>>(x, theta);
    combine_kernel<<<NQ / 256, 256>>>();
    gemm_kernel<<<dim3(EE / 64, BB * SS / 64), 128, GEMM_SMEM>>>(w, (float*)d_out);
}

// round 12
// speedup vs baseline: 1.2076x; 1.0210x over previous
#include <cuda_runtime.h>
#include <cstdint>

#define BB 4
#define SS 1024
#define HH 32
#define DD 8
#define EE 256
constexpr int NROWS = BB * SS * HH;            // 131072
constexpr int NQ = BB * HH * SS;               // 131072 (rows x heads)

// Scratch (allocation-free rule: __device__ globals)
__device__ float g_att[BB * SS * EE];          // [B,S,E] attention out, 4 MB
__device__ float g_po[2][NQ][8];               // split-K partial o, 8 MB
__device__ float g_pl[2][NQ];                  // split-K partial l, 1 MB

// ---------- packed f32x2 helpers (Blackwell dual FP32 datapath) ----------
__device__ __forceinline__ unsigned long long pack2(float lo, float hi) {
    unsigned long long r;
    asm("mov.b64 %0, {%1, %2};" : "=l"(r) : "f"(lo), "f"(hi));
    return r;
}
__device__ __forceinline__ void unpack2(unsigned long long v, float& lo, float& hi) {
    asm("mov.b64 {%0, %1}, %2;" : "=f"(lo), "=f"(hi) : "l"(v));
}
__device__ __forceinline__ unsigned long long ffma2(unsigned long long a,
                                                    unsigned long long b,
                                                    unsigned long long c) {
    unsigned long long d;
    asm("fma.rn.f32x2 %0, %1, %2, %3;" : "=l"(d) : "l"(a), "l"(b), "l"(c));
    return d;
}
__device__ __forceinline__ unsigned long long fadd2(unsigned long long a,
                                                    unsigned long long b) {
    unsigned long long d;
    asm("add.rn.f32x2 %0, %1, %2;" : "=l"(d) : "l"(a), "l"(b));
    return d;
}
__device__ __forceinline__ float ex2(float x) {
    float y;
    asm("ex2.approx.ftz.f32 %0, %1;" : "=f"(y) : "f"(x));
    return y;
}

// ---------------------------------------------------------------------------
// Attention, split-K(2) + 2 queries/thread (halves SMEM read traffic, the
// measured R11 binder). Circuit closed form:
//   <Z_w> = prod_{j=0..w} cos(x_j+th_j) (w>=1), <Z_0> = prod_{j=1..7}.
// Grid (128 heads, 4 q-slabs, 2 key-halves) x 128 threads = 1024 blocks.
// Phase 1: block builds its 512-key half tile, pair-packed:
//          sF[p*16 + 2d + lane] = Z[2p+lane][d]  (16 KB).
// Each thread computes its TWO q rows closed-form from x directly.
// Phase 2: per key-pair load (4 x LDS.128, shared by both queries):
// per query an 8-step ffma2 chain -> two dots, ex2/lane, AV lane partials.
// |score| <= sqrt(8): no max subtraction. Unnormalized partials out.
// ---------------------------------------------------------------------------
__global__ void __launch_bounds__(128) attn_kernel(const float* __restrict__ x,
                                                   const float* __restrict__ theta) {
    __shared__ float sF[512 * 8];   // 16 KB pair-packed half tile

    int bh   = blockIdx.x;          // 0..127 (b*32 + h)
    int slab = blockIdx.y;          // 0..3 (256 queries each)
    int kh   = blockIdx.z;          // 0..1 key half
    int tid  = threadIdx.x;
    int b = bh >> 5, h = bh & 31;

    float th[8];
#pragma unroll
    for (int d = 0; d < 8; d++) th[d] = theta[d];

    // Phase 1: key half tile (512 rows, 4/thread)
    for (int j = tid; j < 512; j += 128) {
        int row = kh * 512 + j;
        const float4* gx = reinterpret_cast<const float4*>(
            x + ((size_t)(b * SS + row) * EE + h * DD));
        float4 xa = gx[0];
        float4 xb = gx[1];

        float c[8];
        c[0] = cosf(xa.x + th[0]);
        c[1] = cosf(xa.y + th[1]);
        c[2] = cosf(xa.z + th[2]);
        c[3] = cosf(xa.w + th[3]);
        c[4] = cosf(xb.x + th[4]);
        c[5] = cosf(xb.y + th[5]);
        c[6] = cosf(xb.z + th[6]);
        c[7] = cosf(xb.w + th[7]);

        float z[8];
        float p = c[0];
#pragma unroll
        for (int w = 1; w < 8; w++) { p *= c[w]; z[w] = p; }
        float s = c[7];
#pragma unroll
        for (int w = 6; w >= 1; w--) s *= c[w];
        z[0] = s;

        int base = (j >> 1) * 16 + (j & 1);
#pragma unroll
        for (int d = 0; d < 8; d++) sF[base + 2 * d] = z[d];
    }

    // This thread's two query rows, computed closed-form directly.
    const float kS = 1.4426950408889634f / 2.8284271247461903f;  // log2(e)/sqrt(8)
    int q0 = slab * 256 + tid * 2;              // queries q0, q0+1
    unsigned long long q2[2][8];
#pragma unroll
    for (int qi = 0; qi < 2; qi++) {
        const float4* gx = reinterpret_cast<const float4*>(
            x + ((size_t)(b * SS + q0 + qi) * EE + h * DD));
        float4 xa = gx[0];
        float4 xb = gx[1];

        float c[8];
        c[0] = cosf(xa.x + th[0]);
        c[1] = cosf(xa.y + th[1]);
        c[2] = cosf(xa.z + th[2]);
        c[3] = cosf(xa.w + th[3]);
        c[4] = cosf(xb.x + th[4]);
        c[5] = cosf(xb.y + th[5]);
        c[6] = cosf(xb.z + th[6]);
        c[7] = cosf(xb.w + th[7]);

        float z[8];
        float p = c[0];
#pragma unroll
        for (int w = 1; w < 8; w++) { p *= c[w]; z[w] = p; }
        float s = c[7];
#pragma unroll
        for (int w = 6; w >= 1; w--) s *= c[w];
        z[0] = s;
#pragma unroll
        for (int d = 0; d < 8; d++) {
            float qv = z[d] * kS;
            q2[qi][d] = pack2(qv, qv);
        }
    }
    __syncthreads();

    unsigned long long o[2][8];
#pragma unroll
    for (int qi = 0; qi < 2; qi++)
#pragma unroll
        for (int d = 0; d < 8; d++) o[qi][d] = 0ULL;
    unsigned long long l2[2] = {0ULL, 0ULL};

    const ulonglong2* kp2 = reinterpret_cast<const ulonglong2*>(sF);

#pragma unroll 2
    for (int p = 0; p < 256; p++) {
        // one key-pair load, shared by both queries
        ulonglong2 w01 = kp2[p * 4 + 0];
        ulonglong2 w23 = kp2[p * 4 + 1];
        ulonglong2 w45 = kp2[p * 4 + 2];
        ulonglong2 w67 = kp2[p * 4 + 3];

        // two independent score chains (ILP)
        unsigned long long s0a = ffma2(q2[0][0], w01.x, 0ULL);
        unsigned long long s1a = ffma2(q2[1][0], w01.x, 0ULL);
        s0a = ffma2(q2[0][1], w01.y, s0a);
        s1a = ffma2(q2[1][1], w01.y, s1a);
        s0a = ffma2(q2[0][2], w23.x, s0a);
        s1a = ffma2(q2[1][2], w23.x, s1a);
        s0a = ffma2(q2[0][3], w23.y, s0a);
        s1a = ffma2(q2[1][3], w23.y, s1a);
        s0a = ffma2(q2[0][4], w45.x, s0a);
        s1a = ffma2(q2[1][4], w45.x, s1a);
        s0a = ffma2(q2[0][5], w45.y, s0a);
        s1a = ffma2(q2[1][5], w45.y, s1a);
        s0a = ffma2(q2[0][6], w67.x, s0a);
        s1a = ffma2(q2[1][6], w67.x, s1a);
        s0a = ffma2(q2[0][7], w67.y, s0a);
        s1a = ffma2(q2[1][7], w67.y, s1a);

        float a0, a1, b0, b1;
        unpack2(s0a, a0, a1);
        unpack2(s1a, b0, b1);
        unsigned long long pp0 = pack2(ex2(a0), ex2(a1));
        unsigned long long pp1 = pack2(ex2(b0), ex2(b1));

        l2[0] = fadd2(l2[0], pp0);
        l2[1] = fadd2(l2[1], pp1);
        o[0][0] = ffma2(pp0, w01.x, o[0][0]);
        o[1][0] = ffma2(pp1, w01.x, o[1][0]);
        o[0][1] = ffma2(pp0, w01.y, o[0][1]);
        o[1][1] = ffma2(pp1, w01.y, o[1][1]);
        o[0][2] = ffma2(pp0, w23.x, o[0][2]);
        o[1][2] = ffma2(pp1, w23.x, o[1][2]);
        o[0][3] = ffma2(pp0, w23.y, o[0][3]);
        o[1][3] = ffma2(pp1, w23.y, o[1][3]);
        o[0][4] = ffma2(pp0, w45.x, o[0][4]);
        o[1][4] = ffma2(pp1, w45.x, o[1][4]);
        o[0][5] = ffma2(pp0, w45.y, o[0][5]);
        o[1][5] = ffma2(pp1, w45.y, o[1][5]);
        o[0][6] = ffma2(pp0, w67.x, o[0][6]);
        o[1][6] = ffma2(pp1, w67.x, o[1][6]);
        o[0][7] = ffma2(pp0, w67.y, o[0][7]);
        o[1][7] = ffma2(pp1, w67.y, o[1][7]);
    }

#pragma unroll
    for (int qi = 0; qi < 2; qi++) {
        float ll, lh;
        unpack2(l2[qi], ll, lh);

        float r[8];
#pragma unroll
        for (int d = 0; d < 8; d++) {
            float lo, hi;
            unpack2(o[qi][d], lo, hi);
            r[d] = lo + hi;
        }

        int rowid = bh * SS + q0 + qi;
        float* po = &g_po[kh][rowid][0];
        *reinterpret_cast<float4*>(po)     = make_float4(r[0], r[1], r[2], r[3]);
        *reinterpret_cast<float4*>(po + 4) = make_float4(r[4], r[5], r[6], r[7]);
        g_pl[kh][rowid] = ll + lh;
    }
}

// ---------------------------------------------------------------------------
// Combine: sum the two key-half partials, normalize, scatter to [B,S,E].
// ---------------------------------------------------------------------------
__global__ void __launch_bounds__(256) combine_kernel() {
    int n = blockIdx.x * 256 + threadIdx.x;    // 0..131071

    const float4* p0 = reinterpret_cast<const float4*>(&g_po[0][n][0]);
    const float4* p1 = reinterpret_cast<const float4*>(&g_po[1][n][0]);
    float4 a0 = p0[0], a1 = p0[1];
    float4 b0 = p1[0], b1 = p1[1];
    float inv = 1.f / (g_pl[0][n] + g_pl[1][n]);

    int bh = n >> 10, sq = n & 1023;
    int b = bh >> 5, h = bh & 31;
    float* dst = g_att + ((size_t)(b * SS + sq)) * EE + h * DD;
    *reinterpret_cast<float4*>(dst) = make_float4(
        (a0.x + b0.x) * inv, (a0.y + b0.y) * inv,
        (a0.z + b0.z) * inv, (a0.w + b0.w) * inv);
    *reinterpret_cast<float4*>(dst + 4) = make_float4(
        (a1.x + b1.x) * inv, (a1.y + b1.y) * inv,
        (a1.z + b1.z) * inv, (a1.w + b1.w) * inv);
}

// ---------------------------------------------------------------------------
// GEMM: out = g_att @ W^T.  M=4096, N=256, K=256, fp32.  (unchanged)
// Tile 64m x 64n, 128 threads, micro 4m x 8n. Full B tile transposed in
// 64 KB dynamic SMEM, ONE sync; A streamed GMEM->regs with k8 prefetch.
// ---------------------------------------------------------------------------
__global__ void __launch_bounds__(128) gemm_kernel(const float* __restrict__ W,
                                                   float* __restrict__ out) {
    extern __shared__ float BsF[];     // 64 KB: BsF[k*64 + n_local]

    int tid = threadIdx.x;
    int tx = tid & 7;
    int ty = tid >> 3;
    int n0 = blockIdx.x * 64, m0 = blockIdx.y * 64;

#pragma unroll
    for (int it = 0; it < 32; it++) {
        int idx = tid + it * 128;
        int r  = idx & 63;
        int c4 = idx >> 6;
        float4 v = *reinterpret_cast<const float4*>(
            &W[(size_t)(n0 + r) * EE + c4 * 4]);
        BsF[(c4 * 4 + 0) * 64 + r] = v.x;
        BsF[(c4 * 4 + 1) * 64 + r] = v.y;
        BsF[(c4 * 4 + 2) * 64 + r] = v.z;
        BsF[(c4 * 4 + 3) * 64 + r] = v.w;
    }
    __syncthreads();

    unsigned long long acc[4][4];
#pragma unroll
    for (int i = 0; i < 4; i++)
#pragma unroll
        for (int j = 0; j < 4; j++) acc[i][j] = 0ULL;

    const float* gA[4];
#pragma unroll
    for (int i = 0; i < 4; i++)
        gA[i] = &g_att[(size_t)(m0 + ty * 4 + i) * EE];

    const unsigned long long* Bk = reinterpret_cast<const unsigned long long*>(BsF);

    float4 cur[4][2];
#pragma unroll
    for (int i = 0; i < 4; i++) {
        cur[i][0] = *reinterpret_cast<const float4*>(gA[i] + 0);
        cur[i][1] = *reinterpret_cast<const float4*>(gA[i] + 4);
    }

    for (int k8 = 0; k8 < EE; k8 += 8) {
        float4 nxt[4][2];
        if (k8 + 8 < EE) {
#pragma unroll
            for (int i = 0; i < 4; i++) {
                nxt[i][0] = *reinterpret_cast<const float4*>(gA[i] + k8 + 8);
                nxt[i][1] = *reinterpret_cast<const float4*>(gA[i] + k8 + 12);
            }
        }

#pragma unroll
        for (int q = 0; q < 2; q++) {
#pragma unroll
            for (int kk = 0; kk < 4; kk++) {
                int k = k8 + q * 4 + kk;
                unsigned long long b0 = Bk[k * 32 + tx];
                unsigned long long b1 = Bk[k * 32 + tx + 8];
                unsigned long long b2 = Bk[k * 32 + tx + 16];
                unsigned long long b3 = Bk[k * 32 + tx + 24];
#pragma unroll
                for (int i = 0; i < 4; i++) {
                    float av = (kk == 0) ? cur[i][q].x :
                               (kk == 1) ? cur[i][q].y :
                               (kk == 2) ? cur[i][q].z : cur[i][q].w;
                    unsigned long long ad = pack2(av, av);
                    acc[i][0] = ffma2(ad, b0, acc[i][0]);
                    acc[i][1] = ffma2(ad, b1, acc[i][1]);
                    acc[i][2] = ffma2(ad, b2, acc[i][2]);
                    acc[i][3] = ffma2(ad, b3, acc[i][3]);
                }
            }
        }

        if (k8 + 8 < EE) {
#pragma unroll
            for (int i = 0; i < 4; i++) {
                cur[i][0] = nxt[i][0];
                cur[i][1] = nxt[i][1];
            }
        }
    }

#pragma unroll
    for (int i = 0; i < 4; i++) {
        float* row = &out[(size_t)(m0 + ty * 4 + i) * EE + n0];
#pragma unroll
        for (int j = 0; j < 4; j++) {
            float lo, hi;
            unpack2(acc[i][j], lo, hi);
            *reinterpret_cast<float2*>(row + 2 * tx + 16 * j) = make_float2(lo, hi);
        }
    }
}

// ---------------------------------------------------------------------------
constexpr int GEMM_SMEM = 64 * EE * 4;   // 65536 bytes

extern "C" void kernel_launch(void* const* d_in, const int* in_sizes, int n_in,
                              void* d_out, int out_size) {
    const float* x = nullptr;
    const float* theta = nullptr;
    const float* w = nullptr;
    for (int i = 0; i < n_in; i++) {
        if (in_sizes[i] == NROWS * DD)      x = (const float*)d_in[i];
        else if (in_sizes[i] == DD)         theta = (const float*)d_in[i];
        else if (in_sizes[i] == EE * EE)    w = (const float*)d_in[i];
    }

    // Host-side attribute set: graph-capture-safe, deterministic.
    cudaFuncSetAttribute(gemm_kernel,
                         cudaFuncAttributeMaxDynamicSharedMemorySize, GEMM_SMEM);

    attn_kernel<<<dim3(BB * HH, 4, 2), 128>>>(x, theta);
    combine_kernel<<<NQ / 256, 256>>>();
    gemm_kernel<<<dim3(EE / 64, BB * SS / 64), 128, GEMM_SMEM>>>(w, (float*)d_out);
}